// round 7
// baseline (speedup 1.0000x reference)
#include <cuda_runtime.h>

#define NN   100000
#define NE   1000000
#define NG   2048
#define HID  64
#define ODIM 128

#define SCAN_T   256
#define SCAN_C   4
#define SCAN_NPB (SCAN_T * SCAN_C)                  // 1024 nodes per block
#define SCAN_B   ((NN + SCAN_NPB - 1) / SCAN_NPB)   // 98 blocks

__device__ float d_dinv[NN];
__device__ int   d_cnt_in[NN];     // in-degree (edges only)
__device__ int   d_row[NN];        // CSR row offsets (exclusive prefix of cnt_in)
__device__ int   d_fill[NN];       // slot counters for CSR build
__device__ int   d_csrc[NE];       // CSR: src node per slot
__device__ float d_cw[NE];         // CSR: edge norm per slot
__device__ float d_h[NN * HID];    // x @ W1
__device__ float d_g[NN * HID];    // relu(h1) @ W2
__device__ float d_pool[NG * HID]; // per-graph sums
__device__ float d_cnt[NG];        // per-graph node counts
__device__ int   d_bsum[SCAN_B];
__device__ int   d_boff[SCAN_B];
__device__ int   d_toff[SCAN_B * SCAN_T];

__device__ __forceinline__ void red_v4(float* ap, float a, float b, float c, float d) {
    asm volatile("red.global.add.v4.f32 [%0], {%1, %2, %3, %4};"
                 :: "l"(ap), "f"(a), "f"(b), "f"(c), "f"(d) : "memory");
}

__global__ void k_zero() {
    int i = blockIdx.x * blockDim.x + threadIdx.x;
    if (i < NN) { d_cnt_in[i] = 0; d_fill[i] = 0; }
    if (i < NG * HID / 4)
        reinterpret_cast<float4*>(d_pool)[i] = make_float4(0.f, 0.f, 0.f, 0.f);
    if (i < NG) d_cnt[i] = 0.f;
}

__global__ void k_hist(const int* __restrict__ dst) {
    int i = blockIdx.x * blockDim.x + threadIdx.x;
    if (i < NE) atomicAdd(&d_cnt_in[dst[i]], 1);
}

__global__ void k_dinv() {
    int i = blockIdx.x * blockDim.x + threadIdx.x;
    if (i < NN) d_dinv[i] = rsqrtf((float)(d_cnt_in[i] + 1));  // +1 self-loop
}

// ---- 3-phase decoupled scan of d_cnt_in -> d_row ----
__global__ void __launch_bounds__(SCAN_T) k_scanA() {
    __shared__ int sh[SCAN_T];
    int b = blockIdx.x, tid = threadIdx.x;
    int base = b * SCAN_NPB + tid * SCAN_C;
    int s = 0;
#pragma unroll
    for (int i = 0; i < SCAN_C; i++) {
        int idx = base + i;
        if (idx < NN) s += d_cnt_in[idx];
    }
    sh[tid] = s;
    __syncthreads();
    for (int off = 1; off < SCAN_T; off <<= 1) {
        int t = (tid >= off) ? sh[tid - off] : 0;
        __syncthreads();
        sh[tid] += t;
        __syncthreads();
    }
    d_toff[b * SCAN_T + tid] = sh[tid] - s;
    if (tid == SCAN_T - 1) d_bsum[b] = sh[tid];
}

__global__ void __launch_bounds__(128) k_scanB() {
    __shared__ int sh[128];
    int tid = threadIdx.x;
    int s = (tid < SCAN_B) ? d_bsum[tid] : 0;
    sh[tid] = s;
    __syncthreads();
    for (int off = 1; off < 128; off <<= 1) {
        int t = (tid >= off) ? sh[tid - off] : 0;
        __syncthreads();
        sh[tid] += t;
        __syncthreads();
    }
    if (tid < SCAN_B) d_boff[tid] = sh[tid] - s;
}

__global__ void __launch_bounds__(SCAN_T) k_scanC() {
    int b = blockIdx.x, tid = threadIdx.x;
    int run = d_boff[b] + d_toff[b * SCAN_T + tid];
    int base = b * SCAN_NPB + tid * SCAN_C;
#pragma unroll
    for (int i = 0; i < SCAN_C; i++) {
        int idx = base + i;
        if (idx < NN) { d_row[idx] = run; run += d_cnt_in[idx]; }
    }
}

__global__ void k_build(const int* __restrict__ src, const int* __restrict__ dst) {
    int e = blockIdx.x * blockDim.x + threadIdx.x;
    if (e >= NE) return;
    int s = src[e], d = dst[e];
    int slot = d_row[d] + atomicAdd(&d_fill[d], 1);
    d_csrc[slot] = s;
    d_cw[slot] = d_dinv[s] * d_dinv[d];
}

// h = x @ W1   (x: [NN,5], W1: [5,64]); 16 lanes/node, float4 stores
__global__ void k_xw1(const float* __restrict__ x, const float* __restrict__ W1) {
    __shared__ float W1s[5 * HID];
    int tid = threadIdx.x;
    for (int i = tid; i < 5 * HID; i += blockDim.x) W1s[i] = W1[i];
    __syncthreads();
    int t = blockIdx.x * blockDim.x + tid;
    int n = t >> 4, c = t & 15;
    if (n >= NN) return;
    float xv[5];
#pragma unroll
    for (int k = 0; k < 5; k++) xv[k] = x[n * 5 + k];
    float o[4];
#pragma unroll
    for (int j = 0; j < 4; j++) {
        float s = 0.f;
#pragma unroll
        for (int k = 0; k < 5; k++) s += xv[k] * W1s[k * HID + c * 4 + j];
        o[j] = s;
    }
    *reinterpret_cast<float4*>(&d_h[(size_t)n * HID + c * 4]) =
        make_float4(o[0], o[1], o[2], o[3]);
}

// 4-way unrolled CSR gather: acc += sum_j w_j * feat[src_j][c*4 .. c*4+3]
__device__ __forceinline__ void gather4(const float* __restrict__ feat,
                                        int start, int deg, int c,
                                        float& a0, float& a1, float& a2, float& a3) {
    int j = 0;
    for (; j + 4 <= deg; j += 4) {
        int   s0 = __ldg(&d_csrc[start + j + 0]);
        int   s1 = __ldg(&d_csrc[start + j + 1]);
        int   s2 = __ldg(&d_csrc[start + j + 2]);
        int   s3 = __ldg(&d_csrc[start + j + 3]);
        float w0 = __ldg(&d_cw[start + j + 0]);
        float w1 = __ldg(&d_cw[start + j + 1]);
        float w2 = __ldg(&d_cw[start + j + 2]);
        float w3 = __ldg(&d_cw[start + j + 3]);
        float4 v0 = *reinterpret_cast<const float4*>(&feat[(size_t)s0 * HID + c * 4]);
        float4 v1 = *reinterpret_cast<const float4*>(&feat[(size_t)s1 * HID + c * 4]);
        float4 v2 = *reinterpret_cast<const float4*>(&feat[(size_t)s2 * HID + c * 4]);
        float4 v3 = *reinterpret_cast<const float4*>(&feat[(size_t)s3 * HID + c * 4]);
        a0 += v0.x * w0; a1 += v0.y * w0; a2 += v0.z * w0; a3 += v0.w * w0;
        a0 += v1.x * w1; a1 += v1.y * w1; a2 += v1.z * w1; a3 += v1.w * w1;
        a0 += v2.x * w2; a1 += v2.y * w2; a2 += v2.z * w2; a3 += v2.w * w2;
        a0 += v3.x * w3; a1 += v3.y * w3; a2 += v3.z * w3; a3 += v3.w * w3;
    }
    for (; j < deg; j++) {
        int   s = __ldg(&d_csrc[start + j]);
        float w = __ldg(&d_cw[start + j]);
        float4 v = *reinterpret_cast<const float4*>(&feat[(size_t)s * HID + c * 4]);
        a0 += v.x * w; a1 += v.y * w; a2 += v.z * w; a3 += v.w * w;
    }
}

// layer 1 fused: agg = CSR-gather(h) + self-loop; h1 = relu(agg + b1); g = h1 @ W2
__global__ void __launch_bounds__(256) k_layer1(const float* __restrict__ b1,
                                                const float* __restrict__ W2) {
    __shared__ float W2s[HID * HID];
    __shared__ float h1s[16 * HID];
    __shared__ float b1s[HID];
    int tid = threadIdx.x;
    for (int i = tid; i < HID * HID; i += 256) W2s[i] = W2[i];
    if (tid < HID) b1s[tid] = b1[tid];
    __syncthreads();

    int nl = tid >> 4, c = tid & 15;
    int node = blockIdx.x * 16 + nl;
    if (node < NN) {
        int start = d_row[node], deg = d_cnt_in[node];
        float a0 = 0.f, a1 = 0.f, a2 = 0.f, a3 = 0.f;
        gather4(d_h, start, deg, c, a0, a1, a2, a3);
        float di = d_dinv[node];
        float sl = di * di;
        float4 hv = *reinterpret_cast<const float4*>(&d_h[(size_t)node * HID + c * 4]);
        h1s[nl * HID + c * 4 + 0] = fmaxf(a0 + hv.x * sl + b1s[c * 4 + 0], 0.f);
        h1s[nl * HID + c * 4 + 1] = fmaxf(a1 + hv.y * sl + b1s[c * 4 + 1], 0.f);
        h1s[nl * HID + c * 4 + 2] = fmaxf(a2 + hv.z * sl + b1s[c * 4 + 2], 0.f);
        h1s[nl * HID + c * 4 + 3] = fmaxf(a3 + hv.w * sl + b1s[c * 4 + 3], 0.f);
    } else {
#pragma unroll
        for (int j = 0; j < 4; j++) h1s[nl * HID + c * 4 + j] = 0.f;
    }
    __syncthreads();

    if (node < NN) {
        float o0 = 0.f, o1 = 0.f, o2 = 0.f, o3 = 0.f;
#pragma unroll
        for (int k = 0; k < HID; k++) {
            float hv = h1s[nl * HID + k];
            o0 += hv * W2s[k * HID + c * 4 + 0];
            o1 += hv * W2s[k * HID + c * 4 + 1];
            o2 += hv * W2s[k * HID + c * 4 + 2];
            o3 += hv * W2s[k * HID + c * 4 + 3];
        }
        *reinterpret_cast<float4*>(&d_g[(size_t)node * HID + c * 4]) =
            make_float4(o0, o1, o2, o3);
    }
}

// layer 2 fused: agg = CSR-gather(g) + self-loop; h2 = relu(agg + b2);
// pool[batch[n]] += h2 (red.v4); cnt[batch[n]] += 1
__global__ void __launch_bounds__(256) k_layer2(const float* __restrict__ b2,
                                                const int* __restrict__ batch) {
    int t = blockIdx.x * blockDim.x + threadIdx.x;
    int n = t >> 4, c = t & 15;
    if (n >= NN) return;
    int start = d_row[n], deg = d_cnt_in[n];
    float a0 = 0.f, a1 = 0.f, a2 = 0.f, a3 = 0.f;
    gather4(d_g, start, deg, c, a0, a1, a2, a3);
    float di = d_dinv[n];
    float sl = di * di;
    float4 gv = *reinterpret_cast<const float4*>(&d_g[(size_t)n * HID + c * 4]);
    float o0 = fmaxf(a0 + gv.x * sl + b2[c * 4 + 0], 0.f);
    float o1 = fmaxf(a1 + gv.y * sl + b2[c * 4 + 1], 0.f);
    float o2 = fmaxf(a2 + gv.z * sl + b2[c * 4 + 2], 0.f);
    float o3 = fmaxf(a3 + gv.w * sl + b2[c * 4 + 3], 0.f);
    int g = batch[n];
    red_v4(&d_pool[g * HID + c * 4], o0, o1, o2, o3);
    if (c == 0) atomicAdd(&d_cnt[g], 1.0f);
}

// per-graph: pooled = pool/max(cnt,1); z = relu(pooled@W3+b3); out = z@W4+b4
__global__ void k_head(const float* __restrict__ W3, const float* __restrict__ b3,
                       const float* __restrict__ W4, const float* __restrict__ b4,
                       float* __restrict__ out) {
    __shared__ float p[HID];
    __shared__ float z[HID];
    int g = blockIdx.x, tid = threadIdx.x;
    if (tid < HID) {
        float cnt = fmaxf(d_cnt[g], 1.0f);
        p[tid] = d_pool[g * HID + tid] / cnt;
    }
    __syncthreads();
    if (tid < HID) {
        float s = b3[tid];
#pragma unroll
        for (int k = 0; k < HID; k++) s += p[k] * W3[k * HID + tid];
        z[tid] = fmaxf(s, 0.f);
    }
    __syncthreads();
    float s = b4[tid];
#pragma unroll
    for (int k = 0; k < HID; k++) s += z[k] * W4[k * ODIM + tid];
    out[g * ODIM + tid] = s;
}

extern "C" void kernel_launch(void* const* d_in, const int* in_sizes, int n_in,
                              void* d_out, int out_size) {
    const float* x     = (const float*)d_in[0];
    const int*   ei    = (const int*)d_in[1];
    const int*   batch = (const int*)d_in[2];
    const float* W1 = (const float*)d_in[3];
    const float* b1 = (const float*)d_in[4];
    const float* W2 = (const float*)d_in[5];
    const float* b2 = (const float*)d_in[6];
    const float* W3 = (const float*)d_in[7];
    const float* b3 = (const float*)d_in[8];
    const float* W4 = (const float*)d_in[9];
    const float* b4 = (const float*)d_in[10];
    float* out = (float*)d_out;

    const int* src = ei;        // edge_index[0, :]
    const int* dst = ei + NE;   // edge_index[1, :]

    k_zero<<<(NN + 255) / 256, 256>>>();
    k_hist<<<(NE + 255) / 256, 256>>>(dst);
    k_dinv<<<(NN + 255) / 256, 256>>>();
    k_scanA<<<SCAN_B, SCAN_T>>>();
    k_scanB<<<1, 128>>>();
    k_scanC<<<SCAN_B, SCAN_T>>>();
    k_build<<<(NE + 255) / 256, 256>>>(src, dst);
    k_xw1<<<(NN * 16 + 255) / 256, 256>>>(x, W1);
    k_layer1<<<(NN + 15) / 16, 256>>>(b1, W2);
    k_layer2<<<(NN * 16 + 255) / 256, 256>>>(b2, batch);
    k_head<<<NG, 128>>>(W3, b3, W4, b4, out);
}

// round 8
// speedup vs baseline: 1.0326x; 1.0326x over previous
#include <cuda_runtime.h>
#include <cuda_fp16.h>

#define NN   100000
#define NE   1000000
#define NG   2048
#define HID  64
#define ODIM 128

#define SCAN_T   256
#define SCAN_C   4
#define SCAN_NPB (SCAN_T * SCAN_C)                  // 1024 nodes per block
#define SCAN_B   ((NN + SCAN_NPB - 1) / SCAN_NPB)   // 98 blocks

__device__ float  d_dinv[NN];
__device__ int    d_cnt_in[NN];
__device__ int    d_row[NN];
__device__ int    d_fill[NN];
__device__ int    d_csrc[NE];
__device__ float  d_cw[NE];
__device__ float  d_h[NN * HID];     // x @ W1 (fp32, for self-loop)
__device__ __half d_h16[NN * HID];   // fp16 mirror (for gather)
__device__ float  d_g[NN * HID];     // layer-1 out (fp32)
__device__ __half d_g16[NN * HID];   // fp16 mirror
__device__ float  d_pool[NG * HID];
__device__ float  d_cnt[NG];
__device__ int    d_bsum[SCAN_B];
__device__ int    d_boff[SCAN_B];
__device__ int    d_toff[SCAN_B * SCAN_T];

__device__ __forceinline__ void red_v4(float* ap, float a, float b, float c, float d) {
    asm volatile("red.global.add.v4.f32 [%0], {%1, %2, %3, %4};"
                 :: "l"(ap), "f"(a), "f"(b), "f"(c), "f"(d) : "memory");
}

// pack 4 floats -> 2x half2 (uint2)
__device__ __forceinline__ uint2 pack_h4(float a, float b, float c, float d) {
    __half2 lo = __floats2half2_rn(a, b);
    __half2 hi = __floats2half2_rn(c, d);
    uint2 r;
    r.x = *reinterpret_cast<unsigned*>(&lo);
    r.y = *reinterpret_cast<unsigned*>(&hi);
    return r;
}

__global__ void k_zero() {
    int i = blockIdx.x * blockDim.x + threadIdx.x;
    if (i < NN) { d_cnt_in[i] = 0; d_fill[i] = 0; }
    if (i < NG * HID / 4)
        reinterpret_cast<float4*>(d_pool)[i] = make_float4(0.f, 0.f, 0.f, 0.f);
    if (i < NG) d_cnt[i] = 0.f;
}

__global__ void k_hist(const int* __restrict__ dst) {
    int i = blockIdx.x * blockDim.x + threadIdx.x;
    if (i < NE) atomicAdd(&d_cnt_in[dst[i]], 1);
}

__global__ void k_dinv() {
    int i = blockIdx.x * blockDim.x + threadIdx.x;
    if (i < NN) d_dinv[i] = rsqrtf((float)(d_cnt_in[i] + 1));
}

__global__ void __launch_bounds__(SCAN_T) k_scanA() {
    __shared__ int sh[SCAN_T];
    int b = blockIdx.x, tid = threadIdx.x;
    int base = b * SCAN_NPB + tid * SCAN_C;
    int s = 0;
#pragma unroll
    for (int i = 0; i < SCAN_C; i++) {
        int idx = base + i;
        if (idx < NN) s += d_cnt_in[idx];
    }
    sh[tid] = s;
    __syncthreads();
    for (int off = 1; off < SCAN_T; off <<= 1) {
        int t = (tid >= off) ? sh[tid - off] : 0;
        __syncthreads();
        sh[tid] += t;
        __syncthreads();
    }
    d_toff[b * SCAN_T + tid] = sh[tid] - s;
    if (tid == SCAN_T - 1) d_bsum[b] = sh[tid];
}

__global__ void __launch_bounds__(128) k_scanB() {
    __shared__ int sh[128];
    int tid = threadIdx.x;
    int s = (tid < SCAN_B) ? d_bsum[tid] : 0;
    sh[tid] = s;
    __syncthreads();
    for (int off = 1; off < 128; off <<= 1) {
        int t = (tid >= off) ? sh[tid - off] : 0;
        __syncthreads();
        sh[tid] += t;
        __syncthreads();
    }
    if (tid < SCAN_B) d_boff[tid] = sh[tid] - s;
}

__global__ void __launch_bounds__(SCAN_T) k_scanC() {
    int b = blockIdx.x, tid = threadIdx.x;
    int run = d_boff[b] + d_toff[b * SCAN_T + tid];
    int base = b * SCAN_NPB + tid * SCAN_C;
#pragma unroll
    for (int i = 0; i < SCAN_C; i++) {
        int idx = base + i;
        if (idx < NN) { d_row[idx] = run; run += d_cnt_in[idx]; }
    }
}

__global__ void k_build(const int* __restrict__ src, const int* __restrict__ dst) {
    int e = blockIdx.x * blockDim.x + threadIdx.x;
    if (e >= NE) return;
    int s = src[e], d = dst[e];
    int slot = d_row[d] + atomicAdd(&d_fill[d], 1);
    d_csrc[slot] = s;
    d_cw[slot] = d_dinv[s] * d_dinv[d];
}

// h = x @ W1; writes fp32 + fp16 mirror
__global__ void k_xw1(const float* __restrict__ x, const float* __restrict__ W1) {
    __shared__ float W1s[5 * HID];
    int tid = threadIdx.x;
    for (int i = tid; i < 5 * HID; i += blockDim.x) W1s[i] = W1[i];
    __syncthreads();
    int t = blockIdx.x * blockDim.x + tid;
    int n = t >> 4, c = t & 15;
    if (n >= NN) return;
    float xv[5];
#pragma unroll
    for (int k = 0; k < 5; k++) xv[k] = x[n * 5 + k];
    float o[4];
#pragma unroll
    for (int j = 0; j < 4; j++) {
        float s = 0.f;
#pragma unroll
        for (int k = 0; k < 5; k++) s += xv[k] * W1s[k * HID + c * 4 + j];
        o[j] = s;
    }
    size_t base = (size_t)n * HID + c * 4;
    *reinterpret_cast<float4*>(&d_h[base]) = make_float4(o[0], o[1], o[2], o[3]);
    *reinterpret_cast<uint2*>(&d_h16[base]) = pack_h4(o[0], o[1], o[2], o[3]);
}

// CSR gather from fp16 features: 16 lanes/node, 4 channels/lane (8 B loads)
__device__ __forceinline__ void gather_h16(const __half* __restrict__ feat,
                                           int start, int deg, int c,
                                           float& a0, float& a1, float& a2, float& a3) {
    int j = 0;
    for (; j + 2 <= deg; j += 2) {
        int   s0 = __ldg(&d_csrc[start + j + 0]);
        int   s1 = __ldg(&d_csrc[start + j + 1]);
        float w0 = __ldg(&d_cw[start + j + 0]);
        float w1 = __ldg(&d_cw[start + j + 1]);
        uint2 u0 = *reinterpret_cast<const uint2*>(&feat[(size_t)s0 * HID + c * 4]);
        uint2 u1 = *reinterpret_cast<const uint2*>(&feat[(size_t)s1 * HID + c * 4]);
        float2 l0 = __half22float2(*reinterpret_cast<__half2*>(&u0.x));
        float2 h0 = __half22float2(*reinterpret_cast<__half2*>(&u0.y));
        float2 l1 = __half22float2(*reinterpret_cast<__half2*>(&u1.x));
        float2 h1 = __half22float2(*reinterpret_cast<__half2*>(&u1.y));
        a0 += l0.x * w0; a1 += l0.y * w0; a2 += h0.x * w0; a3 += h0.y * w0;
        a0 += l1.x * w1; a1 += l1.y * w1; a2 += h1.x * w1; a3 += h1.y * w1;
    }
    if (j < deg) {
        int   s = __ldg(&d_csrc[start + j]);
        float w = __ldg(&d_cw[start + j]);
        uint2 u = *reinterpret_cast<const uint2*>(&feat[(size_t)s * HID + c * 4]);
        float2 l = __half22float2(*reinterpret_cast<__half2*>(&u.x));
        float2 h = __half22float2(*reinterpret_cast<__half2*>(&u.y));
        a0 += l.x * w; a1 += l.y * w; a2 += h.x * w; a3 += h.y * w;
    }
}

// layer 1 fused: gather(h16) + self-loop(fp32) -> relu -> @W2 -> g (fp32+fp16)
__global__ void __launch_bounds__(256) k_layer1(const float* __restrict__ b1,
                                                const float* __restrict__ W2) {
    __shared__ float W2s[HID * HID];
    __shared__ float h1s[16 * HID];
    __shared__ float b1s[HID];
    int tid = threadIdx.x;
    for (int i = tid; i < HID * HID; i += 256) W2s[i] = W2[i];
    if (tid < HID) b1s[tid] = b1[tid];
    __syncthreads();

    int nl = tid >> 4, c = tid & 15;
    int node = blockIdx.x * 16 + nl;
    if (node < NN) {
        int start = d_row[node], deg = d_cnt_in[node];
        float a0 = 0.f, a1 = 0.f, a2 = 0.f, a3 = 0.f;
        gather_h16(d_h16, start, deg, c, a0, a1, a2, a3);
        float di = d_dinv[node];
        float sl = di * di;
        float4 hv = *reinterpret_cast<const float4*>(&d_h[(size_t)node * HID + c * 4]);
        h1s[nl * HID + c * 4 + 0] = fmaxf(a0 + hv.x * sl + b1s[c * 4 + 0], 0.f);
        h1s[nl * HID + c * 4 + 1] = fmaxf(a1 + hv.y * sl + b1s[c * 4 + 1], 0.f);
        h1s[nl * HID + c * 4 + 2] = fmaxf(a2 + hv.z * sl + b1s[c * 4 + 2], 0.f);
        h1s[nl * HID + c * 4 + 3] = fmaxf(a3 + hv.w * sl + b1s[c * 4 + 3], 0.f);
    } else {
#pragma unroll
        for (int j = 0; j < 4; j++) h1s[nl * HID + c * 4 + j] = 0.f;
    }
    __syncthreads();

    if (node < NN) {
        float o0 = 0.f, o1 = 0.f, o2 = 0.f, o3 = 0.f;
#pragma unroll
        for (int k = 0; k < HID; k++) {
            float hv = h1s[nl * HID + k];
            o0 += hv * W2s[k * HID + c * 4 + 0];
            o1 += hv * W2s[k * HID + c * 4 + 1];
            o2 += hv * W2s[k * HID + c * 4 + 2];
            o3 += hv * W2s[k * HID + c * 4 + 3];
        }
        size_t base = (size_t)node * HID + c * 4;
        *reinterpret_cast<float4*>(&d_g[base]) = make_float4(o0, o1, o2, o3);
        *reinterpret_cast<uint2*>(&d_g16[base]) = pack_h4(o0, o1, o2, o3);
    }
}

// layer 2 fused: gather(g16) + self-loop(fp32) -> relu -> pool (red.v4)
__global__ void __launch_bounds__(256) k_layer2(const float* __restrict__ b2,
                                                const int* __restrict__ batch) {
    int t = blockIdx.x * blockDim.x + threadIdx.x;
    int n = t >> 4, c = t & 15;
    if (n >= NN) return;
    int start = d_row[n], deg = d_cnt_in[n];
    float a0 = 0.f, a1 = 0.f, a2 = 0.f, a3 = 0.f;
    gather_h16(d_g16, start, deg, c, a0, a1, a2, a3);
    float di = d_dinv[n];
    float sl = di * di;
    float4 gv = *reinterpret_cast<const float4*>(&d_g[(size_t)n * HID + c * 4]);
    float o0 = fmaxf(a0 + gv.x * sl + b2[c * 4 + 0], 0.f);
    float o1 = fmaxf(a1 + gv.y * sl + b2[c * 4 + 1], 0.f);
    float o2 = fmaxf(a2 + gv.z * sl + b2[c * 4 + 2], 0.f);
    float o3 = fmaxf(a3 + gv.w * sl + b2[c * 4 + 3], 0.f);
    int g = batch[n];
    red_v4(&d_pool[g * HID + c * 4], o0, o1, o2, o3);
    if (c == 0) atomicAdd(&d_cnt[g], 1.0f);
}

__global__ void k_head(const float* __restrict__ W3, const float* __restrict__ b3,
                       const float* __restrict__ W4, const float* __restrict__ b4,
                       float* __restrict__ out) {
    __shared__ float p[HID];
    __shared__ float z[HID];
    int g = blockIdx.x, tid = threadIdx.x;
    if (tid < HID) {
        float cnt = fmaxf(d_cnt[g], 1.0f);
        p[tid] = d_pool[g * HID + tid] / cnt;
    }
    __syncthreads();
    if (tid < HID) {
        float s = b3[tid];
#pragma unroll
        for (int k = 0; k < HID; k++) s += p[k] * W3[k * HID + tid];
        z[tid] = fmaxf(s, 0.f);
    }
    __syncthreads();
    float s = b4[tid];
#pragma unroll
    for (int k = 0; k < HID; k++) s += z[k] * W4[k * ODIM + tid];
    out[g * ODIM + tid] = s;
}

extern "C" void kernel_launch(void* const* d_in, const int* in_sizes, int n_in,
                              void* d_out, int out_size) {
    const float* x     = (const float*)d_in[0];
    const int*   ei    = (const int*)d_in[1];
    const int*   batch = (const int*)d_in[2];
    const float* W1 = (const float*)d_in[3];
    const float* b1 = (const float*)d_in[4];
    const float* W2 = (const float*)d_in[5];
    const float* b2 = (const float*)d_in[6];
    const float* W3 = (const float*)d_in[7];
    const float* b3 = (const float*)d_in[8];
    const float* W4 = (const float*)d_in[9];
    const float* b4 = (const float*)d_in[10];
    float* out = (float*)d_out;

    const int* src = ei;
    const int* dst = ei + NE;

    k_zero<<<(NN + 255) / 256, 256>>>();
    k_hist<<<(NE + 255) / 256, 256>>>(dst);
    k_dinv<<<(NN + 255) / 256, 256>>>();
    k_scanA<<<SCAN_B, SCAN_T>>>();
    k_scanB<<<1, 128>>>();
    k_scanC<<<SCAN_B, SCAN_T>>>();
    k_build<<<(NE + 255) / 256, 256>>>(src, dst);
    k_xw1<<<(NN * 16 + 255) / 256, 256>>>(x, W1);
    k_layer1<<<(NN + 15) / 16, 256>>>(b1, W2);
    k_layer2<<<(NN * 16 + 255) / 256, 256>>>(b2, batch);
    k_head<<<NG, 128>>>(W3, b3, W4, b4, out);
}

// round 9
// speedup vs baseline: 1.0617x; 1.0281x over previous
#include <cuda_runtime.h>
#include <cuda_fp16.h>

#define NN   100000
#define NE   1000000
#define NG   2048
#define HID  64
#define ODIM 128

#define SCAN_T   256
#define SCAN_C   4
#define SCAN_NPB (SCAN_T * SCAN_C)                  // 1024 nodes per block
#define SCAN_B   ((NN + SCAN_NPB - 1) / SCAN_NPB)   // 98 blocks

__device__ float  d_dinv[NN];
__device__ int    d_cnt_in[NN];    // zeroed by tail of previous run (and at init)
__device__ int    d_row[NN];
__device__ int    d_fill[NN];      // zeroed by tail of previous run
__device__ int    d_csrc[NE];
__device__ float  d_cw[NE];
__device__ float  d_h[NN * HID];
__device__ __half d_h16[NN * HID];
__device__ float  d_g[NN * HID];
__device__ __half d_g16[NN * HID];
__device__ float  d_pool[NG * HID]; // zeroed by tail of previous run
__device__ float  d_cnt[NG];        // zeroed by tail of previous run
__device__ int    d_bsum[SCAN_B];
__device__ int    d_toff[SCAN_B * SCAN_T];

__device__ __forceinline__ void red_v4(float* ap, float a, float b, float c, float d) {
    asm volatile("red.global.add.v4.f32 [%0], {%1, %2, %3, %4};"
                 :: "l"(ap), "f"(a), "f"(b), "f"(c), "f"(d) : "memory");
}

__device__ __forceinline__ uint2 pack_h4(float a, float b, float c, float d) {
    __half2 lo = __floats2half2_rn(a, b);
    __half2 hi = __floats2half2_rn(c, d);
    uint2 r;
    r.x = *reinterpret_cast<unsigned*>(&lo);
    r.y = *reinterpret_cast<unsigned*>(&hi);
    return r;
}

// ── 1. fused: degree histogram (edges) + h = x @ W1 (nodes) ──
// grid = 6250 x 256 = 1.6M threads; hist uses first 1M, xw1 uses all (16/node)
__global__ void __launch_bounds__(256) k_hist_xw1(const int* __restrict__ dst,
                                                  const float* __restrict__ x,
                                                  const float* __restrict__ W1) {
    __shared__ float W1s[5 * HID];
    int tid = threadIdx.x;
    for (int i = tid; i < 5 * HID; i += blockDim.x) W1s[i] = W1[i];
    __syncthreads();

    int t = blockIdx.x * blockDim.x + tid;
    if (t < NE) atomicAdd(&d_cnt_in[dst[t]], 1);

    int n = t >> 4, c = t & 15;
    if (n >= NN) return;
    float xv[5];
#pragma unroll
    for (int k = 0; k < 5; k++) xv[k] = x[n * 5 + k];
    float o[4];
#pragma unroll
    for (int j = 0; j < 4; j++) {
        float s = 0.f;
#pragma unroll
        for (int k = 0; k < 5; k++) s += xv[k] * W1s[k * HID + c * 4 + j];
        o[j] = s;
    }
    size_t base = (size_t)n * HID + c * 4;
    *reinterpret_cast<float4*>(&d_h[base]) = make_float4(o[0], o[1], o[2], o[3]);
    *reinterpret_cast<uint2*>(&d_h16[base]) = pack_h4(o[0], o[1], o[2], o[3]);
}

// ── 2. scan phase A + dinv: block-local sums/offsets + rsqrt(deg+1) ──
__global__ void __launch_bounds__(SCAN_T) k_scanA_dinv() {
    __shared__ int sh[SCAN_T];
    int b = blockIdx.x, tid = threadIdx.x;
    int base = b * SCAN_NPB + tid * SCAN_C;
    int s = 0;
#pragma unroll
    for (int i = 0; i < SCAN_C; i++) {
        int idx = base + i;
        if (idx < NN) {
            int cv = d_cnt_in[idx];
            s += cv;
            d_dinv[idx] = rsqrtf((float)(cv + 1));  // +1 self-loop
        }
    }
    sh[tid] = s;
    __syncthreads();
    for (int off = 1; off < SCAN_T; off <<= 1) {
        int t = (tid >= off) ? sh[tid - off] : 0;
        __syncthreads();
        sh[tid] += t;
        __syncthreads();
    }
    d_toff[b * SCAN_T + tid] = sh[tid] - s;
    if (tid == SCAN_T - 1) d_bsum[b] = sh[tid];
}

// ── 3. scan phase B+C fused: each block scans the 98 block totals in smem,
//       then writes its row offsets ──
__global__ void __launch_bounds__(SCAN_T) k_scanC() {
    __shared__ int sh[SCAN_T];
    __shared__ int sv[SCAN_T];
    int b = blockIdx.x, tid = threadIdx.x;
    int v = (tid < SCAN_B) ? d_bsum[tid] : 0;
    sh[tid] = v;
    sv[tid] = v;
    __syncthreads();
    for (int off = 1; off < SCAN_T; off <<= 1) {
        int t = (tid >= off) ? sh[tid - off] : 0;
        __syncthreads();
        sh[tid] += t;
        __syncthreads();
    }
    int boff = sh[b] - sv[b];  // exclusive prefix of block totals at b
    int run = boff + d_toff[b * SCAN_T + tid];
    int base = b * SCAN_NPB + tid * SCAN_C;
#pragma unroll
    for (int i = 0; i < SCAN_C; i++) {
        int idx = base + i;
        if (idx < NN) { d_row[idx] = run; run += d_cnt_in[idx]; }
    }
}

// ── 4. CSR build ──
__global__ void k_build(const int* __restrict__ src, const int* __restrict__ dst) {
    int e = blockIdx.x * blockDim.x + threadIdx.x;
    if (e >= NE) return;
    int s = src[e], d = dst[e];
    int slot = d_row[d] + atomicAdd(&d_fill[d], 1);
    d_csrc[slot] = s;
    d_cw[slot] = d_dinv[s] * d_dinv[d];
}

// CSR gather from fp16 features: 16 lanes/node, 4 channels/lane (8 B loads)
__device__ __forceinline__ void gather_h16(const __half* __restrict__ feat,
                                           int start, int deg, int c,
                                           float& a0, float& a1, float& a2, float& a3) {
    int j = 0;
    for (; j + 2 <= deg; j += 2) {
        int   s0 = __ldg(&d_csrc[start + j + 0]);
        int   s1 = __ldg(&d_csrc[start + j + 1]);
        float w0 = __ldg(&d_cw[start + j + 0]);
        float w1 = __ldg(&d_cw[start + j + 1]);
        uint2 u0 = *reinterpret_cast<const uint2*>(&feat[(size_t)s0 * HID + c * 4]);
        uint2 u1 = *reinterpret_cast<const uint2*>(&feat[(size_t)s1 * HID + c * 4]);
        float2 l0 = __half22float2(*reinterpret_cast<__half2*>(&u0.x));
        float2 h0 = __half22float2(*reinterpret_cast<__half2*>(&u0.y));
        float2 l1 = __half22float2(*reinterpret_cast<__half2*>(&u1.x));
        float2 h1 = __half22float2(*reinterpret_cast<__half2*>(&u1.y));
        a0 += l0.x * w0; a1 += l0.y * w0; a2 += h0.x * w0; a3 += h0.y * w0;
        a0 += l1.x * w1; a1 += l1.y * w1; a2 += h1.x * w1; a3 += h1.y * w1;
    }
    if (j < deg) {
        int   s = __ldg(&d_csrc[start + j]);
        float w = __ldg(&d_cw[start + j]);
        uint2 u = *reinterpret_cast<const uint2*>(&feat[(size_t)s * HID + c * 4]);
        float2 l = __half22float2(*reinterpret_cast<__half2*>(&u.x));
        float2 h = __half22float2(*reinterpret_cast<__half2*>(&u.y));
        a0 += l.x * w; a1 += l.y * w; a2 += h.x * w; a3 += h.y * w;
    }
}

// ── 5. layer 1: gather(h16) + self-loop -> relu -> @W2 -> g (fp32+fp16) ──
__global__ void __launch_bounds__(256) k_layer1(const float* __restrict__ b1,
                                                const float* __restrict__ W2) {
    __shared__ float W2s[HID * HID];
    __shared__ float h1s[16 * HID];
    __shared__ float b1s[HID];
    int tid = threadIdx.x;
    for (int i = tid; i < HID * HID; i += 256) W2s[i] = W2[i];
    if (tid < HID) b1s[tid] = b1[tid];
    __syncthreads();

    int nl = tid >> 4, c = tid & 15;
    int node = blockIdx.x * 16 + nl;
    if (node < NN) {
        int start = d_row[node], deg = d_cnt_in[node];
        float a0 = 0.f, a1 = 0.f, a2 = 0.f, a3 = 0.f;
        gather_h16(d_h16, start, deg, c, a0, a1, a2, a3);
        float di = d_dinv[node];
        float sl = di * di;
        float4 hv = *reinterpret_cast<const float4*>(&d_h[(size_t)node * HID + c * 4]);
        h1s[nl * HID + c * 4 + 0] = fmaxf(a0 + hv.x * sl + b1s[c * 4 + 0], 0.f);
        h1s[nl * HID + c * 4 + 1] = fmaxf(a1 + hv.y * sl + b1s[c * 4 + 1], 0.f);
        h1s[nl * HID + c * 4 + 2] = fmaxf(a2 + hv.z * sl + b1s[c * 4 + 2], 0.f);
        h1s[nl * HID + c * 4 + 3] = fmaxf(a3 + hv.w * sl + b1s[c * 4 + 3], 0.f);
    } else {
#pragma unroll
        for (int j = 0; j < 4; j++) h1s[nl * HID + c * 4 + j] = 0.f;
    }
    __syncthreads();

    if (node < NN) {
        float o0 = 0.f, o1 = 0.f, o2 = 0.f, o3 = 0.f;
#pragma unroll
        for (int k = 0; k < HID; k++) {
            float hv = h1s[nl * HID + k];
            o0 += hv * W2s[k * HID + c * 4 + 0];
            o1 += hv * W2s[k * HID + c * 4 + 1];
            o2 += hv * W2s[k * HID + c * 4 + 2];
            o3 += hv * W2s[k * HID + c * 4 + 3];
        }
        size_t base = (size_t)node * HID + c * 4;
        *reinterpret_cast<float4*>(&d_g[base]) = make_float4(o0, o1, o2, o3);
        *reinterpret_cast<uint2*>(&d_g16[base]) = pack_h4(o0, o1, o2, o3);
    }
}

// ── 6. layer 2: gather(g16) + self-loop -> relu -> pool (red.v4) ──
__global__ void __launch_bounds__(256) k_layer2(const float* __restrict__ b2,
                                                const int* __restrict__ batch) {
    int t = blockIdx.x * blockDim.x + threadIdx.x;
    int n = t >> 4, c = t & 15;
    if (n >= NN) return;
    int start = d_row[n], deg = d_cnt_in[n];
    float a0 = 0.f, a1 = 0.f, a2 = 0.f, a3 = 0.f;
    gather_h16(d_g16, start, deg, c, a0, a1, a2, a3);
    float di = d_dinv[n];
    float sl = di * di;
    float4 gv = *reinterpret_cast<const float4*>(&d_g[(size_t)n * HID + c * 4]);
    float o0 = fmaxf(a0 + gv.x * sl + b2[c * 4 + 0], 0.f);
    float o1 = fmaxf(a1 + gv.y * sl + b2[c * 4 + 1], 0.f);
    float o2 = fmaxf(a2 + gv.z * sl + b2[c * 4 + 2], 0.f);
    float o3 = fmaxf(a3 + gv.w * sl + b2[c * 4 + 3], 0.f);
    int g = batch[n];
    red_v4(&d_pool[g * HID + c * 4], o0, o1, o2, o3);
    if (c == 0) atomicAdd(&d_cnt[g], 1.0f);
}

// ── 7. head + tail-restore: out = relu(pool/cnt @ W3 + b3) @ W4 + b4;
//       then zero pool/cnt/cnt_in/fill for the next replay ──
__global__ void __launch_bounds__(128) k_head(const float* __restrict__ W3,
                                              const float* __restrict__ b3,
                                              const float* __restrict__ W4,
                                              const float* __restrict__ b4,
                                              float* __restrict__ out) {
    __shared__ float p[HID];
    __shared__ float z[HID];
    int g = blockIdx.x, tid = threadIdx.x;
    if (tid < HID) {
        float cnt = fmaxf(d_cnt[g], 1.0f);
        p[tid] = d_pool[g * HID + tid] / cnt;
    }
    __syncthreads();
    // tail-restore (pool row already consumed into smem)
    if (tid < HID) d_pool[g * HID + tid] = 0.f;
    if (tid == 0)  d_cnt[g] = 0.f;
    {
        int i = g * 128 + tid;           // 262144 threads cover NN=100000
        if (i < NN) { d_cnt_in[i] = 0; d_fill[i] = 0; }
    }
    if (tid < HID) {
        float s = b3[tid];
#pragma unroll
        for (int k = 0; k < HID; k++) s += p[k] * W3[k * HID + tid];
        z[tid] = fmaxf(s, 0.f);
    }
    __syncthreads();
    float s = b4[tid];
#pragma unroll
    for (int k = 0; k < HID; k++) s += z[k] * W4[k * ODIM + tid];
    out[g * ODIM + tid] = s;
}

extern "C" void kernel_launch(void* const* d_in, const int* in_sizes, int n_in,
                              void* d_out, int out_size) {
    const float* x     = (const float*)d_in[0];
    const int*   ei    = (const int*)d_in[1];
    const int*   batch = (const int*)d_in[2];
    const float* W1 = (const float*)d_in[3];
    const float* b1 = (const float*)d_in[4];
    const float* W2 = (const float*)d_in[5];
    const float* b2 = (const float*)d_in[6];
    const float* W3 = (const float*)d_in[7];
    const float* b3 = (const float*)d_in[8];
    const float* W4 = (const float*)d_in[9];
    const float* b4 = (const float*)d_in[10];
    float* out = (float*)d_out;

    const int* src = ei;
    const int* dst = ei + NE;

    k_hist_xw1<<<(NN * 16 + 255) / 256, 256>>>(dst, x, W1);
    k_scanA_dinv<<<SCAN_B, SCAN_T>>>();
    k_scanC<<<SCAN_B, SCAN_T>>>();
    k_build<<<(NE + 255) / 256, 256>>>(src, dst);
    k_layer1<<<(NN + 15) / 16, 256>>>(b1, W2);
    k_layer2<<<(NN * 16 + 255) / 256, 256>>>(b2, batch);
    k_head<<<NG, 128>>>(W3, b3, W4, b4, out);
}

// round 10
// speedup vs baseline: 1.2161x; 1.1455x over previous
#include <cuda_runtime.h>
#include <cuda_fp16.h>

#define NN   100000
#define NE   1000000
#define NG   2048
#define HID  64
#define ODIM 128

#define SCAN_T   256
#define SCAN_C   4
#define SCAN_NPB (SCAN_T * SCAN_C)                  // 1024 nodes per block
#define SCAN_B   ((NN + SCAN_NPB - 1) / SCAN_NPB)   // 98 blocks

__device__ float  d_dinv[NN];
__device__ int    d_cnt_in[NN];    // zeroed by tail of previous run
__device__ int    d_row[NN];
__device__ int    d_fill[NN];      // zeroed by tail of previous run
__device__ int2   d_edge[NE];      // CSR: packed {src, __float_as_int(norm)}
__device__ __half d_h16[NN * HID]; // x @ W1 (fp16)
__device__ __half d_g16[NN * HID]; // layer-1 out (fp16)
__device__ float  d_pool[NG * HID]; // zeroed by tail of previous run
__device__ float  d_cnt[NG];        // zeroed by tail of previous run
__device__ int    d_bsum[SCAN_B];
__device__ int    d_toff[SCAN_B * SCAN_T];

__device__ __forceinline__ void red_v4(float* ap, float a, float b, float c, float d) {
    asm volatile("red.global.add.v4.f32 [%0], {%1, %2, %3, %4};"
                 :: "l"(ap), "f"(a), "f"(b), "f"(c), "f"(d) : "memory");
}

__device__ __forceinline__ uint2 pack_h4(float a, float b, float c, float d) {
    __half2 lo = __floats2half2_rn(a, b);
    __half2 hi = __floats2half2_rn(c, d);
    uint2 r;
    r.x = *reinterpret_cast<unsigned*>(&lo);
    r.y = *reinterpret_cast<unsigned*>(&hi);
    return r;
}

__device__ __forceinline__ void unpack_h4(uint2 u, float& a, float& b, float& c, float& d) {
    float2 l = __half22float2(*reinterpret_cast<__half2*>(&u.x));
    float2 h = __half22float2(*reinterpret_cast<__half2*>(&u.y));
    a = l.x; b = l.y; c = h.x; d = h.y;
}

// ── 1. fused: degree histogram (edges) + h16 = x @ W1 (nodes) ──
__global__ void __launch_bounds__(256) k_hist_xw1(const int* __restrict__ dst,
                                                  const float* __restrict__ x,
                                                  const float* __restrict__ W1) {
    __shared__ float W1s[5 * HID];
    int tid = threadIdx.x;
    for (int i = tid; i < 5 * HID; i += blockDim.x) W1s[i] = W1[i];
    __syncthreads();

    int t = blockIdx.x * blockDim.x + tid;
    if (t < NE) atomicAdd(&d_cnt_in[dst[t]], 1);

    int n = t >> 4, c = t & 15;
    if (n >= NN) return;
    float xv[5];
#pragma unroll
    for (int k = 0; k < 5; k++) xv[k] = x[n * 5 + k];
    float o[4];
#pragma unroll
    for (int j = 0; j < 4; j++) {
        float s = 0.f;
#pragma unroll
        for (int k = 0; k < 5; k++) s += xv[k] * W1s[k * HID + c * 4 + j];
        o[j] = s;
    }
    *reinterpret_cast<uint2*>(&d_h16[(size_t)n * HID + c * 4]) =
        pack_h4(o[0], o[1], o[2], o[3]);
}

// ── 2. scan phase A + dinv ──
__global__ void __launch_bounds__(SCAN_T) k_scanA_dinv() {
    __shared__ int sh[SCAN_T];
    int b = blockIdx.x, tid = threadIdx.x;
    int base = b * SCAN_NPB + tid * SCAN_C;
    int s = 0;
#pragma unroll
    for (int i = 0; i < SCAN_C; i++) {
        int idx = base + i;
        if (idx < NN) {
            int cv = d_cnt_in[idx];
            s += cv;
            d_dinv[idx] = rsqrtf((float)(cv + 1));  // +1 self-loop
        }
    }
    sh[tid] = s;
    __syncthreads();
    for (int off = 1; off < SCAN_T; off <<= 1) {
        int t = (tid >= off) ? sh[tid - off] : 0;
        __syncthreads();
        sh[tid] += t;
        __syncthreads();
    }
    d_toff[b * SCAN_T + tid] = sh[tid] - s;
    if (tid == SCAN_T - 1) d_bsum[b] = sh[tid];
}

// ── 3. scan phase B+C fused ──
__global__ void __launch_bounds__(SCAN_T) k_scanC() {
    __shared__ int sh[SCAN_T];
    __shared__ int sv[SCAN_T];
    int b = blockIdx.x, tid = threadIdx.x;
    int v = (tid < SCAN_B) ? d_bsum[tid] : 0;
    sh[tid] = v;
    sv[tid] = v;
    __syncthreads();
    for (int off = 1; off < SCAN_T; off <<= 1) {
        int t = (tid >= off) ? sh[tid - off] : 0;
        __syncthreads();
        sh[tid] += t;
        __syncthreads();
    }
    int boff = sh[b] - sv[b];
    int run = boff + d_toff[b * SCAN_T + tid];
    int base = b * SCAN_NPB + tid * SCAN_C;
#pragma unroll
    for (int i = 0; i < SCAN_C; i++) {
        int idx = base + i;
        if (idx < NN) { d_row[idx] = run; run += d_cnt_in[idx]; }
    }
}

// ── 4. CSR build: one packed 8 B store per edge ──
__global__ void k_build(const int* __restrict__ src, const int* __restrict__ dst) {
    int e = blockIdx.x * blockDim.x + threadIdx.x;
    if (e >= NE) return;
    int s = src[e], d = dst[e];
    int slot = d_row[d] + atomicAdd(&d_fill[d], 1);
    float w = d_dinv[s] * d_dinv[d];
    d_edge[slot] = make_int2(s, __float_as_int(w));
}

// CSR gather from fp16 features via packed edge records
__device__ __forceinline__ void gather_h16(const __half* __restrict__ feat,
                                           int start, int deg, int c,
                                           float& a0, float& a1, float& a2, float& a3) {
    int j = 0;
    for (; j + 2 <= deg; j += 2) {
        int2 e0 = __ldg(&d_edge[start + j + 0]);
        int2 e1 = __ldg(&d_edge[start + j + 1]);
        float w0 = __int_as_float(e0.y);
        float w1 = __int_as_float(e1.y);
        uint2 u0 = *reinterpret_cast<const uint2*>(&feat[(size_t)e0.x * HID + c * 4]);
        uint2 u1 = *reinterpret_cast<const uint2*>(&feat[(size_t)e1.x * HID + c * 4]);
        float p0, p1, p2, p3, q0, q1, q2, q3;
        unpack_h4(u0, p0, p1, p2, p3);
        unpack_h4(u1, q0, q1, q2, q3);
        a0 += p0 * w0; a1 += p1 * w0; a2 += p2 * w0; a3 += p3 * w0;
        a0 += q0 * w1; a1 += q1 * w1; a2 += q2 * w1; a3 += q3 * w1;
    }
    if (j < deg) {
        int2 e = __ldg(&d_edge[start + j]);
        float w = __int_as_float(e.y);
        uint2 u = *reinterpret_cast<const uint2*>(&feat[(size_t)e.x * HID + c * 4]);
        float p0, p1, p2, p3;
        unpack_h4(u, p0, p1, p2, p3);
        a0 += p0 * w; a1 += p1 * w; a2 += p2 * w; a3 += p3 * w;
    }
}

// ── 5. layer 1: gather(h16) + self-loop(h16) -> relu -> @W2 -> g16 ──
__global__ void __launch_bounds__(256) k_layer1(const float* __restrict__ b1,
                                                const float* __restrict__ W2) {
    __shared__ float W2s[HID * HID];
    __shared__ float h1s[16 * HID];
    __shared__ float b1s[HID];
    int tid = threadIdx.x;
    for (int i = tid; i < HID * HID; i += 256) W2s[i] = W2[i];
    if (tid < HID) b1s[tid] = b1[tid];
    __syncthreads();

    int nl = tid >> 4, c = tid & 15;
    int node = blockIdx.x * 16 + nl;
    if (node < NN) {
        int start = d_row[node], deg = d_cnt_in[node];
        float a0 = 0.f, a1 = 0.f, a2 = 0.f, a3 = 0.f;
        gather_h16(d_h16, start, deg, c, a0, a1, a2, a3);
        float di = d_dinv[node];
        float sl = di * di;
        uint2 u = *reinterpret_cast<const uint2*>(&d_h16[(size_t)node * HID + c * 4]);
        float h0, h1, h2, h3;
        unpack_h4(u, h0, h1, h2, h3);
        h1s[nl * HID + c * 4 + 0] = fmaxf(a0 + h0 * sl + b1s[c * 4 + 0], 0.f);
        h1s[nl * HID + c * 4 + 1] = fmaxf(a1 + h1 * sl + b1s[c * 4 + 1], 0.f);
        h1s[nl * HID + c * 4 + 2] = fmaxf(a2 + h2 * sl + b1s[c * 4 + 2], 0.f);
        h1s[nl * HID + c * 4 + 3] = fmaxf(a3 + h3 * sl + b1s[c * 4 + 3], 0.f);
    } else {
#pragma unroll
        for (int j = 0; j < 4; j++) h1s[nl * HID + c * 4 + j] = 0.f;
    }
    __syncthreads();

    if (node < NN) {
        float o0 = 0.f, o1 = 0.f, o2 = 0.f, o3 = 0.f;
#pragma unroll
        for (int k = 0; k < HID; k++) {
            float hv = h1s[nl * HID + k];
            o0 += hv * W2s[k * HID + c * 4 + 0];
            o1 += hv * W2s[k * HID + c * 4 + 1];
            o2 += hv * W2s[k * HID + c * 4 + 2];
            o3 += hv * W2s[k * HID + c * 4 + 3];
        }
        *reinterpret_cast<uint2*>(&d_g16[(size_t)node * HID + c * 4]) =
            pack_h4(o0, o1, o2, o3);
    }
}

// ── 6. layer 2: gather(g16) + self-loop(g16) -> relu -> pool (red.v4) ──
__global__ void __launch_bounds__(256) k_layer2(const float* __restrict__ b2,
                                                const int* __restrict__ batch) {
    int t = blockIdx.x * blockDim.x + threadIdx.x;
    int n = t >> 4, c = t & 15;
    if (n >= NN) return;
    int start = d_row[n], deg = d_cnt_in[n];
    float a0 = 0.f, a1 = 0.f, a2 = 0.f, a3 = 0.f;
    gather_h16(d_g16, start, deg, c, a0, a1, a2, a3);
    float di = d_dinv[n];
    float sl = di * di;
    uint2 u = *reinterpret_cast<const uint2*>(&d_g16[(size_t)n * HID + c * 4]);
    float g0, g1, g2, g3;
    unpack_h4(u, g0, g1, g2, g3);
    float o0 = fmaxf(a0 + g0 * sl + b2[c * 4 + 0], 0.f);
    float o1 = fmaxf(a1 + g1 * sl + b2[c * 4 + 1], 0.f);
    float o2 = fmaxf(a2 + g2 * sl + b2[c * 4 + 2], 0.f);
    float o3 = fmaxf(a3 + g3 * sl + b2[c * 4 + 3], 0.f);
    int g = batch[n];
    red_v4(&d_pool[g * HID + c * 4], o0, o1, o2, o3);
    if (c == 0) atomicAdd(&d_cnt[g], 1.0f);
}

// ── 7. head + tail-restore ──
__global__ void __launch_bounds__(128) k_head(const float* __restrict__ W3,
                                              const float* __restrict__ b3,
                                              const float* __restrict__ W4,
                                              const float* __restrict__ b4,
                                              float* __restrict__ out) {
    __shared__ float p[HID];
    __shared__ float z[HID];
    int g = blockIdx.x, tid = threadIdx.x;
    if (tid < HID) {
        float cnt = fmaxf(d_cnt[g], 1.0f);
        p[tid] = d_pool[g * HID + tid] / cnt;
    }
    __syncthreads();
    if (tid < HID) d_pool[g * HID + tid] = 0.f;
    if (tid == 0)  d_cnt[g] = 0.f;
    {
        int i = g * 128 + tid;           // 262144 threads cover NN=100000
        if (i < NN) { d_cnt_in[i] = 0; d_fill[i] = 0; }
    }
    if (tid < HID) {
        float s = b3[tid];
#pragma unroll
        for (int k = 0; k < HID; k++) s += p[k] * W3[k * HID + tid];
        z[tid] = fmaxf(s, 0.f);
    }
    __syncthreads();
    float s = b4[tid];
#pragma unroll
    for (int k = 0; k < HID; k++) s += z[k] * W4[k * ODIM + tid];
    out[g * ODIM + tid] = s;
}

extern "C" void kernel_launch(void* const* d_in, const int* in_sizes, int n_in,
                              void* d_out, int out_size) {
    const float* x     = (const float*)d_in[0];
    const int*   ei    = (const int*)d_in[1];
    const int*   batch = (const int*)d_in[2];
    const float* W1 = (const float*)d_in[3];
    const float* b1 = (const float*)d_in[4];
    const float* W2 = (const float*)d_in[5];
    const float* b2 = (const float*)d_in[6];
    const float* W3 = (const float*)d_in[7];
    const float* b3 = (const float*)d_in[8];
    const float* W4 = (const float*)d_in[9];
    const float* b4 = (const float*)d_in[10];
    float* out = (float*)d_out;

    const int* src = ei;
    const int* dst = ei + NE;

    k_hist_xw1<<<(NN * 16 + 255) / 256, 256>>>(dst, x, W1);
    k_scanA_dinv<<<SCAN_B, SCAN_T>>>();
    k_scanC<<<SCAN_B, SCAN_T>>>();
    k_build<<<(NE + 255) / 256, 256>>>(src, dst);
    k_layer1<<<(NN + 15) / 16, 256>>>(b1, W2);
    k_layer2<<<(NN * 16 + 255) / 256, 256>>>(b2, batch);
    k_head<<<NG, 128>>>(W3, b3, W4, b4, out);
}